// round 16
// baseline (speedup 1.0000x reference)
#include <cuda_runtime.h>
#include <cuda_fp16.h>
#include <cstdint>

#define MDIM 4096
#define KDIM 4096
#define NDIM 4096
#define BB   32
#define NBCOLS 128
#define KBROWS 128
#define BM   256
#define THREADS 256
#define MAXBLK (KBROWS * NBCOLS)
#define XCONV_BLOCKS (KBROWS * 32)     // 4096
#define WCAP 40                        // w blocks staged in smem (80 KB)
#define SMEM_BYTES (WCAP * 2048)

// ---------------- device scratch ----------------
__device__ int g_cnt[NBCOLS];
__device__ int g_listn[NBCOLS * KBROWS];
__device__ int g_listi[NBCOLS * KBROWS];
// w fragments fp16: [n][nt][lane] -> uint4 = (kc0:r0,r1, kc1:r0,r1)
__device__ uint4 g_wf[(size_t)MAXBLK * 128];
// x A-fragments fp16: [i][t16][kc][lane] -> uint4
__device__ uint4 g_xf[(size_t)KBROWS * 256 * 2 * 32];

__device__ __forceinline__ uint32_t smem_u32(const void* p) {
    uint32_t a;
    asm("{ .reg .u64 t; cvta.to.shared.u64 t, %1; cvt.u32.u64 %0, t; }" : "=r"(a) : "l"(p));
    return a;
}

// ---------------- fused prep kernel ----------------
__global__ __launch_bounds__(THREADS) void prep_kernel(
    const float* __restrict__ x,
    const float* __restrict__ w,
    const int*  __restrict__ idx_i,
    const int*  __restrict__ idx_j,
    int nnz)
{
    __shared__ float sbuf[128 * 32];
    const int bid = blockIdx.x;
    const int tid = threadIdx.x;

    if (bid < XCONV_BLOCKS) {
        // ---------- xconv: fp32 -> fp16 A fragments ----------
        const int i  = bid >> 5;
        const int mc = bid & 31;
        const float4* X4 = reinterpret_cast<const float4*>(x);
        float4* XS4 = reinterpret_cast<float4*>(sbuf);
        #pragma unroll
        for (int t = 0; t < 4; ++t) {
            int idx = tid + t * THREADS;
            int r = idx >> 3, c4 = idx & 7;
            XS4[r * 8 + c4] = X4[(size_t)(mc * 128 + r) * (KDIM / 4) + i * 8 + c4];
        }
        __syncthreads();
        #pragma unroll
        for (int it0 = 0; it0 < 2; ++it0) {
            int it   = tid + it0 * THREADS;
            int lane = it & 31;
            int kc   = (it >> 5) & 1;
            int t16  = it >> 6;
            int gid  = lane >> 2, tig = lane & 3;
            int r0 = t16 * 16 + gid, r1 = r0 + 8;
            int c0 = kc * 16 + 2 * tig;
            int c2 = c0 + 8;
            float f[8];
            f[0] = sbuf[r0 * 32 + c0];  f[1] = sbuf[r0 * 32 + c0 + 1];
            f[2] = sbuf[r1 * 32 + c0];  f[3] = sbuf[r1 * 32 + c0 + 1];
            f[4] = sbuf[r0 * 32 + c2];  f[5] = sbuf[r0 * 32 + c2 + 1];
            f[6] = sbuf[r1 * 32 + c2];  f[7] = sbuf[r1 * 32 + c2 + 1];
            uint4 hv;
            uint32_t* hw = reinterpret_cast<uint32_t*>(&hv);
            #pragma unroll
            for (int p = 0; p < 4; ++p) {
                __half2 hp = __float22half2_rn(make_float2(f[2 * p], f[2 * p + 1]));
                hw[p] = *reinterpret_cast<uint32_t*>(&hp);
            }
            g_xf[((size_t)(i * 256 + mc * 8 + t16) * 2 + kc) * 32 + lane] = hv;
        }
    } else if (bid < XCONV_BLOCKS + nnz) {
        // ---------- wconv: fp32 -> fp16 B fragments ----------
        const int n = bid - XCONV_BLOCKS;
        const float* wn = w + (size_t)n * (BB * BB);
        #pragma unroll
        for (int q = 0; q < 4; ++q) sbuf[tid + q * THREADS] = wn[tid + q * THREADS];
        __syncthreads();
        uint32_t* WF = reinterpret_cast<uint32_t*>(g_wf);
        #pragma unroll
        for (int q = 0; q < 2; ++q) {
            int oi   = tid + q * THREADS;        // 0..511
            int nt   = oi >> 7;
            int lane = (oi >> 2) & 31;
            int word = oi & 3;
            int kc   = word >> 1, reg = word & 1;
            int gid  = lane >> 2, tig = lane & 3;
            int c  = nt * 8 + gid;
            int k0 = kc * 16 + 2 * tig + reg * 8;
            __half2 out = __float22half2_rn(make_float2(sbuf[k0 * BB + c],
                                                        sbuf[(k0 + 1) * BB + c]));
            WF[(size_t)n * 512 + oi] = *reinterpret_cast<uint32_t*>(&out);
        }
    } else {
        // ---------- bucket: one warp per output column ----------
        const int blk  = bid - XCONV_BLOCKS - nnz;
        const int j    = blk * 8 + (tid >> 5);
        const int lane = tid & 31;
        if (j < NBCOLS) {
            int cnt = 0;
            for (int base = 0; base < nnz; base += 32) {
                int n = base + lane;
                bool hit = (n < nnz) && (idx_j[n] == j);
                unsigned m = __ballot_sync(0xFFFFFFFFu, hit);
                if (hit) {
                    int pos = cnt + __popc(m & ((1u << lane) - 1u));
                    g_listn[j * KBROWS + pos] = n;
                    g_listi[j * KBROWS + pos] = idx_i[n];
                }
                cnt += __popc(m);
            }
            if (lane == 0) g_cnt[j] = cnt;
        }
    }
}

// ---------------- main HMMA kernel: smem-w, A prefetch distance 3 ----------------
__global__ __launch_bounds__(THREADS) void bsmm_mma_kernel(float* __restrict__ y)
{
    extern __shared__ __align__(16) char smw[];   // WCAP * 2048 bytes of w fragments
    __shared__ int s_i[KBROWS];
    __shared__ int s_n[KBROWS];

    const int j    = blockIdx.x;
    const int m0   = blockIdx.y * BM;
    const int tid  = threadIdx.x;
    const int wid  = tid >> 5;
    const int lane = tid & 31;
    const int gid  = lane >> 2;
    const int tig  = lane & 3;
    const int t16base = (m0 >> 4) + wid * 2;

    const uint32_t smw_base = smem_u32(smw);
    const int cnt = g_cnt[j];
    const int cw  = min(cnt, WCAP);

    // ---- stage w fragments for first cw entries into smem via cp.async ----
    for (int idx = tid; idx < cw * 128; idx += THREADS) {
        int e = idx >> 7, q = idx & 127;
        int n = __ldg(&g_listn[j * KBROWS + e]);
        const uint4* src = g_wf + (size_t)n * 128 + q;
        asm volatile("cp.async.cg.shared.global [%0], [%1], 16;"
                     :: "r"(smw_base + idx * 16), "l"(src));
    }
    asm volatile("cp.async.commit_group;");
    if (tid < cnt) {
        s_i[tid] = g_listi[j * KBROWS + tid];
        s_n[tid] = g_listn[j * KBROWS + tid];
    }
    asm volatile("cp.async.wait_group 0;");
    __syncthreads();

    float acc[2][4][4];
    #pragma unroll
    for (int s = 0; s < 2; ++s)
        #pragma unroll
        for (int t = 0; t < 4; ++t)
            #pragma unroll
            for (int r = 0; r < 4; ++r) acc[s][t][r] = 0.0f;

    // three statically-named A buffer sets: index [s*2+kc]
    uint4 A0[4], A1[4], A2[4];

    auto ldA = [&](uint4 (&A)[4], int e) {
        const int i = s_i[e];
        #pragma unroll
        for (int s = 0; s < 2; ++s)
            #pragma unroll
            for (int kc = 0; kc < 2; ++kc)
                A[s * 2 + kc] =
                    __ldg(&g_xf[((size_t)(i * 256 + t16base + s) * 2 + kc) * 32 + lane]);
    };

    auto slot = [&](uint4 (&A)[4], int e, int epre) {
        uint4 W[4];
        if (e < WCAP) {
            uint32_t base = smw_base + e * 2048 + lane * 16;
            #pragma unroll
            for (int nt = 0; nt < 4; ++nt)
                asm volatile("ld.shared.v4.u32 {%0,%1,%2,%3}, [%4];"
                             : "=r"(W[nt].x), "=r"(W[nt].y), "=r"(W[nt].z), "=r"(W[nt].w)
                             : "r"(base + nt * 512));
        } else {
            const uint4* wf = g_wf + (size_t)s_n[e] * 128 + lane;
            #pragma unroll
            for (int nt = 0; nt < 4; ++nt) W[nt] = __ldg(&wf[nt * 32]);
        }
        #pragma unroll
        for (int kc = 0; kc < 2; ++kc) {
            #pragma unroll
            for (int nt = 0; nt < 4; ++nt) {
                uint32_t b0 = kc ? W[nt].z : W[nt].x;
                uint32_t b1 = kc ? W[nt].w : W[nt].y;
                #pragma unroll
                for (int s = 0; s < 2; ++s) {
                    const uint4& Af = A[s * 2 + kc];
                    float* d = acc[s][nt];
                    asm volatile(
                        "mma.sync.aligned.m16n8k16.row.col.f32.f16.f16.f32 "
                        "{%0,%1,%2,%3}, {%4,%5,%6,%7}, {%8,%9}, {%0,%1,%2,%3};"
                        : "+f"(d[0]), "+f"(d[1]), "+f"(d[2]), "+f"(d[3])
                        : "r"(Af.x), "r"(Af.y), "r"(Af.z), "r"(Af.w),
                          "r"(b0), "r"(b1));
                }
            }
        }
        // reload this buffer for iteration epre (used 3 slots later)
        ldA(A, epre);
    };

    if (cnt > 0) {
        ldA(A0, 0);
        ldA(A1, min(1, cnt - 1));
        ldA(A2, min(2, cnt - 1));
        int e = 0;
        for (;;) {
            slot(A0, e, min(e + 3, cnt - 1)); if (++e == cnt) break;
            slot(A1, e, min(e + 3, cnt - 1)); if (++e == cnt) break;
            slot(A2, e, min(e + 3, cnt - 1)); if (++e == cnt) break;
        }
    }

    // ---- epilogue ----
    #pragma unroll
    for (int s = 0; s < 2; ++s) {
        #pragma unroll
        for (int nt = 0; nt < 4; ++nt) {
            const float* d = acc[s][nt];
            int row0 = m0 + wid * 32 + s * 16 + gid;
            int col  = j * BB + nt * 8 + tig * 2;
            *reinterpret_cast<float2*>(&y[(size_t)row0 * NDIM + col]) =
                make_float2(d[0], d[1]);
            *reinterpret_cast<float2*>(&y[(size_t)(row0 + 8) * NDIM + col]) =
                make_float2(d[2], d[3]);
        }
    }
}

extern "C" void kernel_launch(void* const* d_in, const int* in_sizes, int n_in,
                              void* d_out, int out_size)
{
    const float* x     = (const float*)d_in[0];
    const float* w     = (const float*)d_in[1];
    const int*   idx_i = (const int*)d_in[2];
    const int*   idx_j = (const int*)d_in[3];
    float*       y     = (float*)d_out;
    const int    nnz   = in_sizes[2];

    cudaFuncSetAttribute(bsmm_mma_kernel,
                         cudaFuncAttributeMaxDynamicSharedMemorySize, SMEM_BYTES);

    prep_kernel<<<XCONV_BLOCKS + nnz + 16, THREADS>>>(x, w, idx_i, idx_j, nnz);

    dim3 grid(NBCOLS, MDIM / BM);
    bsmm_mma_kernel<<<grid, THREADS, SMEM_BYTES>>>(y);
}

// round 17
// speedup vs baseline: 1.0425x; 1.0425x over previous
#include <cuda_runtime.h>
#include <cuda_fp16.h>
#include <cstdint>

#define MDIM 4096
#define KDIM 4096
#define NDIM 4096
#define BB   32
#define NBCOLS 128
#define KBROWS 128
#define BM   256
#define THREADS 256
#define MAXBLK (KBROWS * NBCOLS)
#define XCONV_BLOCKS (KBROWS * 32)     // 4096
#define WCAP 40                        // w blocks staged in smem (80 KB)
#define SMEM_BYTES (WCAP * 2048)
#define XP 36                          // padded smem pitch (floats) for prep staging

// ---------------- device scratch ----------------
__device__ int g_cnt[NBCOLS];
__device__ int g_listn[NBCOLS * KBROWS];
__device__ int g_listi[NBCOLS * KBROWS];
// w fragments fp16: [n][nt][lane] -> uint4 = (kc0:r0,r1, kc1:r0,r1)
__device__ uint4 g_wf[(size_t)MAXBLK * 128];
// x A-fragments fp16: [i][t16][kc][lane] -> uint4
__device__ uint4 g_xf[(size_t)KBROWS * 256 * 2 * 32];

__device__ __forceinline__ uint32_t smem_u32(const void* p) {
    uint32_t a;
    asm("{ .reg .u64 t; cvta.to.shared.u64 t, %1; cvt.u32.u64 %0, t; }" : "=r"(a) : "l"(p));
    return a;
}

// ---------------- fused prep kernel ----------------
__global__ __launch_bounds__(THREADS) void prep_kernel(
    const float* __restrict__ x,
    const float* __restrict__ w,
    const int*  __restrict__ idx_i,
    const int*  __restrict__ idx_j,
    int nnz)
{
    __shared__ float sbuf[128 * XP];   // 18 KB, padded pitch
    const int bid = blockIdx.x;
    const int tid = threadIdx.x;

    if (bid < XCONV_BLOCKS) {
        // ---------- xconv: fp32 -> fp16 A fragments ----------
        const int i  = bid >> 5;
        const int mc = bid & 31;
        const float4* X4 = reinterpret_cast<const float4*>(x);
        #pragma unroll
        for (int t = 0; t < 4; ++t) {
            int idx = tid + t * THREADS;
            int r = idx >> 3, c4 = idx & 7;
            float4 v = X4[(size_t)(mc * 128 + r) * (KDIM / 4) + i * 8 + c4];
            *reinterpret_cast<float4*>(&sbuf[r * XP + c4 * 4]) = v;   // 16B-aligned
        }
        __syncthreads();
        #pragma unroll
        for (int it0 = 0; it0 < 2; ++it0) {
            int it   = tid + it0 * THREADS;
            int lane = it & 31;
            int kc   = (it >> 5) & 1;
            int t16  = it >> 6;
            int gid  = lane >> 2, tig = lane & 3;
            int r0 = t16 * 16 + gid, r1 = r0 + 8;
            int c0 = kc * 16 + 2 * tig;
            int c2 = c0 + 8;
            // 4 x LDS.64, <=2-way conflicts at pitch 36
            float2 p0 = *reinterpret_cast<const float2*>(&sbuf[r0 * XP + c0]);
            float2 p1 = *reinterpret_cast<const float2*>(&sbuf[r1 * XP + c0]);
            float2 p2 = *reinterpret_cast<const float2*>(&sbuf[r0 * XP + c2]);
            float2 p3 = *reinterpret_cast<const float2*>(&sbuf[r1 * XP + c2]);
            uint4 hv;
            uint32_t* hw = reinterpret_cast<uint32_t*>(&hv);
            __half2 h0 = __float22half2_rn(p0);
            __half2 h1 = __float22half2_rn(p1);
            __half2 h2 = __float22half2_rn(p2);
            __half2 h3 = __float22half2_rn(p3);
            hw[0] = *reinterpret_cast<uint32_t*>(&h0);
            hw[1] = *reinterpret_cast<uint32_t*>(&h1);
            hw[2] = *reinterpret_cast<uint32_t*>(&h2);
            hw[3] = *reinterpret_cast<uint32_t*>(&h3);
            g_xf[((size_t)(i * 256 + mc * 8 + t16) * 2 + kc) * 32 + lane] = hv;
        }
    } else if (bid < XCONV_BLOCKS + nnz) {
        // ---------- wconv: fp32 -> fp16 B fragments ----------
        const int n = bid - XCONV_BLOCKS;
        const float* wn = w + (size_t)n * (BB * BB);
        #pragma unroll
        for (int q = 0; q < 4; ++q) sbuf[tid + q * THREADS] = wn[tid + q * THREADS];
        __syncthreads();
        uint32_t* WF = reinterpret_cast<uint32_t*>(g_wf);
        #pragma unroll
        for (int q = 0; q < 2; ++q) {
            int oi   = tid + q * THREADS;        // 0..511
            int nt   = oi >> 7;
            int lane = (oi >> 2) & 31;
            int word = oi & 3;
            int kc   = word >> 1, reg = word & 1;
            int gid  = lane >> 2, tig = lane & 3;
            int c  = nt * 8 + gid;
            int k0 = kc * 16 + 2 * tig + reg * 8;
            __half2 out = __float22half2_rn(make_float2(sbuf[k0 * BB + c],
                                                        sbuf[(k0 + 1) * BB + c]));
            WF[(size_t)n * 512 + oi] = *reinterpret_cast<uint32_t*>(&out);
        }
    } else {
        // ---------- bucket: one warp per output column ----------
        const int blk  = bid - XCONV_BLOCKS - nnz;
        const int j    = blk * 8 + (tid >> 5);
        const int lane = tid & 31;
        if (j < NBCOLS) {
            int cnt = 0;
            for (int base = 0; base < nnz; base += 32) {
                int n = base + lane;
                bool hit = (n < nnz) && (idx_j[n] == j);
                unsigned m = __ballot_sync(0xFFFFFFFFu, hit);
                if (hit) {
                    int pos = cnt + __popc(m & ((1u << lane) - 1u));
                    g_listn[j * KBROWS + pos] = n;
                    g_listi[j * KBROWS + pos] = idx_i[n];
                }
                cnt += __popc(m);
            }
            if (lane == 0) g_cnt[j] = cnt;
        }
    }
}

// ---------------- main HMMA kernel: smem-w, slim addressing, A prefetch x3 ----------------
__global__ __launch_bounds__(THREADS) void bsmm_mma_kernel(float* __restrict__ y)
{
    extern __shared__ __align__(16) char smw[];   // WCAP * 2048 bytes of w fragments
    __shared__ int s_i[KBROWS];
    __shared__ int s_n[KBROWS];

    const int j    = blockIdx.x;
    const int m0   = blockIdx.y * BM;
    const int tid  = threadIdx.x;
    const int wid  = tid >> 5;
    const int lane = tid & 31;
    const int gid  = lane >> 2;
    const int tig  = lane & 3;
    const int t16base = (m0 >> 4) + wid * 2;

    const uint32_t smw_base = smem_u32(smw) + (lane << 4);
    const int cnt = g_cnt[j];
    const int cw  = min(cnt, WCAP);
    const int cnt1 = cnt - 1;
    // per-thread constant part of A address (uint4 units):
    // full index = i*16384 + (t16base+s)*64 + kc*32 + lane
    const uint4* a_base = g_xf + t16base * 64 + lane;

    // ---- stage w fragments for first cw entries into smem via cp.async ----
    {
        const uint32_t smw0 = smem_u32(smw);
        for (int idx = tid; idx < cw * 128; idx += THREADS) {
            int e = idx >> 7, q = idx & 127;
            int n = __ldg(&g_listn[j * KBROWS + e]);
            const uint4* src = g_wf + (size_t)n * 128 + q;
            asm volatile("cp.async.cg.shared.global [%0], [%1], 16;"
                         :: "r"(smw0 + idx * 16), "l"(src));
        }
    }
    asm volatile("cp.async.commit_group;");
    if (tid < cnt) {
        s_i[tid] = g_listi[j * KBROWS + tid];
        s_n[tid] = g_listn[j * KBROWS + tid];
    }
    asm volatile("cp.async.wait_group 0;");
    __syncthreads();

    float acc[2][4][4];
    #pragma unroll
    for (int s = 0; s < 2; ++s)
        #pragma unroll
        for (int t = 0; t < 4; ++t)
            #pragma unroll
            for (int r = 0; r < 4; ++r) acc[s][t][r] = 0.0f;

    // three statically-named A buffer sets: index [s*2+kc]
    uint4 A0[4], A1[4], A2[4];

    auto ldA = [&](uint4 (&A)[4], int e) {
        const uint4* p = a_base + (s_i[e] << 14);
        A[0] = __ldg(p);         // s0 kc0
        A[1] = __ldg(p + 32);    // s0 kc1
        A[2] = __ldg(p + 64);    // s1 kc0
        A[3] = __ldg(p + 96);    // s1 kc1
    };

    auto slot = [&](uint4 (&A)[4], int e, int epre) {
        uint4 W[4];
        if (e < WCAP) {
            uint32_t base = smw_base + (e << 11);
            #pragma unroll
            for (int nt = 0; nt < 4; ++nt)
                asm volatile("ld.shared.v4.u32 {%0,%1,%2,%3}, [%4];"
                             : "=r"(W[nt].x), "=r"(W[nt].y), "=r"(W[nt].z), "=r"(W[nt].w)
                             : "r"(base + nt * 512));
        } else {
            const uint4* wf = g_wf + (size_t)s_n[e] * 128 + lane;
            #pragma unroll
            for (int nt = 0; nt < 4; ++nt) W[nt] = __ldg(&wf[nt * 32]);
        }
        #pragma unroll
        for (int kc = 0; kc < 2; ++kc) {
            #pragma unroll
            for (int nt = 0; nt < 4; ++nt) {
                uint32_t b0 = kc ? W[nt].z : W[nt].x;
                uint32_t b1 = kc ? W[nt].w : W[nt].y;
                #pragma unroll
                for (int s = 0; s < 2; ++s) {
                    const uint4& Af = A[s * 2 + kc];
                    float* d = acc[s][nt];
                    asm volatile(
                        "mma.sync.aligned.m16n8k16.row.col.f32.f16.f16.f32 "
                        "{%0,%1,%2,%3}, {%4,%5,%6,%7}, {%8,%9}, {%0,%1,%2,%3};"
                        : "+f"(d[0]), "+f"(d[1]), "+f"(d[2]), "+f"(d[3])
                        : "r"(Af.x), "r"(Af.y), "r"(Af.z), "r"(Af.w),
                          "r"(b0), "r"(b1));
                }
            }
        }
        // reload this buffer for iteration epre (used 3 slots later)
        ldA(A, epre);
    };

    if (cnt > 0) {
        ldA(A0, 0);
        ldA(A1, min(1, cnt1));
        ldA(A2, min(2, cnt1));
        int e = 0;
        for (;;) {
            slot(A0, e, min(e + 3, cnt1)); if (++e == cnt) break;
            slot(A1, e, min(e + 3, cnt1)); if (++e == cnt) break;
            slot(A2, e, min(e + 3, cnt1)); if (++e == cnt) break;
        }
    }

    // ---- epilogue ----
    #pragma unroll
    for (int s = 0; s < 2; ++s) {
        #pragma unroll
        for (int nt = 0; nt < 4; ++nt) {
            const float* d = acc[s][nt];
            int row0 = m0 + wid * 32 + s * 16 + gid;
            int col  = j * BB + nt * 8 + tig * 2;
            *reinterpret_cast<float2*>(&y[(size_t)row0 * NDIM + col]) =
                make_float2(d[0], d[1]);
            *reinterpret_cast<float2*>(&y[(size_t)(row0 + 8) * NDIM + col]) =
                make_float2(d[2], d[3]);
        }
    }
}

extern "C" void kernel_launch(void* const* d_in, const int* in_sizes, int n_in,
                              void* d_out, int out_size)
{
    const float* x     = (const float*)d_in[0];
    const float* w     = (const float*)d_in[1];
    const int*   idx_i = (const int*)d_in[2];
    const int*   idx_j = (const int*)d_in[3];
    float*       y     = (float*)d_out;
    const int    nnz   = in_sizes[2];

    cudaFuncSetAttribute(bsmm_mma_kernel,
                         cudaFuncAttributeMaxDynamicSharedMemorySize, SMEM_BYTES);

    prep_kernel<<<XCONV_BLOCKS + nnz + 16, THREADS>>>(x, w, idx_i, idx_j, nnz);

    dim3 grid(NBCOLS, MDIM / BM);
    bsmm_mma_kernel<<<grid, THREADS, SMEM_BYTES>>>(y);
}